// round 6
// baseline (speedup 1.0000x reference)
#include <cuda_runtime.h>
#include <cstdint>
#include <cstddef>

// Problem constants
// x: [B=4, C=256, H=256, W=256], tokens M = B*H*W = 262144
// qkv: [M, 768], o/proj: [M, 256]
#define M_TOK 262144
#define CDIM 256
#define HEADS 8
#define HD 32
#define WIN 8
#define TWIN 64           // tokens per window
#define NWIN 4096         // windows total (4 * 32 * 32)

// Scratch (static __device__ arrays — allocation-free per harness rules)
__device__ float g_qkv[(size_t)M_TOK * 768];   // 805 MB
__device__ float g_o[(size_t)M_TOK * CDIM];    // 268 MB
__device__ float g_proj[(size_t)M_TOK * CDIM]; // 268 MB

// ---------------------------------------------------------------------------
// Kernel 1: QKV projection GEMM.
//   out[m, n] = sum_k A[m,k] * w_in[n,k] + b_in[n],  n in [0,768)
//   A[m,k] = x[b, k, h, w] with m = b*65536 + h*256 + w  (column-major in m!)
// Tiles: BM=128, BN=128, BK=16, 256 threads, 8x8 register blocking.
// ---------------------------------------------------------------------------
#define BM 128
#define BN 128
#define BK 16

__global__ __launch_bounds__(256) void qkv_gemm_kernel(
    const float* __restrict__ x, const float* __restrict__ w,
    const float* __restrict__ bias, float* __restrict__ out)
{
    __shared__ float As[BK][BM];
    __shared__ float Bs[BK][BN];

    const int tid = threadIdx.x;
    const int tx = tid & 15;        // 16 col-groups of 8
    const int ty = tid >> 4;        // 16 row-groups of 8
    const int n0 = blockIdx.x * BN; // n tile (6 tiles, fast dim for L2 A-reuse)
    const int m0 = blockIdx.y * BM;

    const int bimg = m0 >> 16;            // batch index (tile never crosses batch)
    const int mm = m0 & 65535;            // h*256 + w offset
    const float* xb = x + (size_t)bimg * 16777216 + mm;

    // A loader: per kt, 2 float4 per thread (rows = k, contiguous in m)
    const int aRow = tid >> 5;            // 0..7 (and +8 for second)
    const int aCol = (tid & 31) * 4;
    // B loader: w[n, k] -> transposed into Bs[k][n]
    const int bRowN = tid >> 1;           // 0..127 (local n)
    const int bSeg = (tid & 1) * 8;       // k sub-offset 0 or 8

    float4 aR0, aR1, bR0, bR1;

    // prologue: tile kt = 0
    aR0 = *(const float4*)(xb + (size_t)(aRow) * 65536 + aCol);
    aR1 = *(const float4*)(xb + (size_t)(aRow + 8) * 65536 + aCol);
    {
        const float* wp = w + (size_t)(n0 + bRowN) * 256 + bSeg;
        bR0 = *(const float4*)(wp);
        bR1 = *(const float4*)(wp + 4);
    }
    *(float4*)&As[aRow][aCol] = aR0;
    *(float4*)&As[aRow + 8][aCol] = aR1;
    Bs[bSeg + 0][bRowN] = bR0.x; Bs[bSeg + 1][bRowN] = bR0.y;
    Bs[bSeg + 2][bRowN] = bR0.z; Bs[bSeg + 3][bRowN] = bR0.w;
    Bs[bSeg + 4][bRowN] = bR1.x; Bs[bSeg + 5][bRowN] = bR1.y;
    Bs[bSeg + 6][bRowN] = bR1.z; Bs[bSeg + 7][bRowN] = bR1.w;
    __syncthreads();

    float acc[8][8];
    #pragma unroll
    for (int i = 0; i < 8; i++)
        #pragma unroll
        for (int j = 0; j < 8; j++) acc[i][j] = 0.f;

    #pragma unroll 1
    for (int kt = 0; kt < 16; kt++) {
        // prefetch next k-tile while computing the current one
        if (kt < 15) {
            const int k0 = (kt + 1) * BK;
            aR0 = *(const float4*)(xb + (size_t)(k0 + aRow) * 65536 + aCol);
            aR1 = *(const float4*)(xb + (size_t)(k0 + aRow + 8) * 65536 + aCol);
            const float* wp = w + (size_t)(n0 + bRowN) * 256 + k0 + bSeg;
            bR0 = *(const float4*)(wp);
            bR1 = *(const float4*)(wp + 4);
        }
        #pragma unroll
        for (int kk = 0; kk < BK; kk++) {
            float a[8], b[8];
            *(float4*)&a[0] = *(float4*)&As[kk][ty * 8];
            *(float4*)&a[4] = *(float4*)&As[kk][ty * 8 + 4];
            *(float4*)&b[0] = *(float4*)&Bs[kk][tx * 8];
            *(float4*)&b[4] = *(float4*)&Bs[kk][tx * 8 + 4];
            #pragma unroll
            for (int i = 0; i < 8; i++)
                #pragma unroll
                for (int j = 0; j < 8; j++)
                    acc[i][j] = fmaf(a[i], b[j], acc[i][j]);
        }
        __syncthreads();
        if (kt < 15) {
            *(float4*)&As[aRow][aCol] = aR0;
            *(float4*)&As[aRow + 8][aCol] = aR1;
            Bs[bSeg + 0][bRowN] = bR0.x; Bs[bSeg + 1][bRowN] = bR0.y;
            Bs[bSeg + 2][bRowN] = bR0.z; Bs[bSeg + 3][bRowN] = bR0.w;
            Bs[bSeg + 4][bRowN] = bR1.x; Bs[bSeg + 5][bRowN] = bR1.y;
            Bs[bSeg + 6][bRowN] = bR1.z; Bs[bSeg + 7][bRowN] = bR1.w;
            __syncthreads();
        }
    }

    // epilogue: bias + store to qkv[m, n]  (row stride 768)
    float4 bv0 = *(const float4*)(bias + n0 + tx * 8);
    float4 bv1 = *(const float4*)(bias + n0 + tx * 8 + 4);
    #pragma unroll
    for (int i = 0; i < 8; i++) {
        size_t row = (size_t)(m0 + ty * 8 + i) * 768 + n0 + tx * 8;
        float4 o0 = make_float4(acc[i][0] + bv0.x, acc[i][1] + bv0.y,
                                acc[i][2] + bv0.z, acc[i][3] + bv0.w);
        float4 o1 = make_float4(acc[i][4] + bv1.x, acc[i][5] + bv1.y,
                                acc[i][6] + bv1.z, acc[i][7] + bv1.w);
        *(float4*)(out + row) = o0;
        *(float4*)(out + row + 4) = o1;
    }
}

// ---------------------------------------------------------------------------
// Kernel 2: windowed attention. One 64-thread block per (window, head).
// Thread i owns query token i of the window: full score row in registers,
// softmax in registers, K/V broadcast from shared memory.
// ---------------------------------------------------------------------------
__global__ __launch_bounds__(64) void attn_kernel(
    const float* __restrict__ qkv, float* __restrict__ o)
{
    const int bid = blockIdx.x;          // 0 .. 32767
    const int head = bid & 7;
    const int win = bid >> 3;
    const int b = win >> 10;             // 1024 windows per image (32x32)
    const int rem = win & 1023;
    const int hn = rem >> 5, wn = rem & 31;

    const int t = threadIdx.x;           // 0..63, token in window
    const int s1 = t >> 3, s2 = t & 7;
    const int m = (b << 16) + ((hn * 8 + s1) << 8) + (wn * 8 + s2);

    __shared__ float4 ks[TWIN][8];
    __shared__ float4 vs[TWIN][8];

    const float* qp = qkv + (size_t)m * 768 + head * 32;
    float4 q[8];
    #pragma unroll
    for (int d = 0; d < 8; d++) {
        q[d]      = ((const float4*)(qp))[d];
        ks[t][d]  = ((const float4*)(qp + 256))[d];
        vs[t][d]  = ((const float4*)(qp + 512))[d];
    }
    __syncthreads();

    // scores: s[j] = (q . k_j) / sqrt(32)
    float s[TWIN];
    #pragma unroll
    for (int j = 0; j < TWIN; j++) {
        float acc = 0.f;
        #pragma unroll
        for (int d = 0; d < 8; d++) {
            float4 kv = ks[j][d];
            acc = fmaf(q[d].x, kv.x, acc);
            acc = fmaf(q[d].y, kv.y, acc);
            acc = fmaf(q[d].z, kv.z, acc);
            acc = fmaf(q[d].w, kv.w, acc);
        }
        s[j] = acc * 0.17677669529663687f;   // 32^-0.5
    }

    // softmax (row is entirely in this thread's registers)
    float mx = s[0];
    #pragma unroll
    for (int j = 1; j < TWIN; j++) mx = fmaxf(mx, s[j]);
    float sum = 0.f;
    #pragma unroll
    for (int j = 0; j < TWIN; j++) { s[j] = __expf(s[j] - mx); sum += s[j]; }
    const float inv = 1.f / sum;

    // o = P V
    float4 acc4[8];
    #pragma unroll
    for (int d = 0; d < 8; d++) acc4[d] = make_float4(0.f, 0.f, 0.f, 0.f);
    #pragma unroll
    for (int j = 0; j < TWIN; j++) {
        const float p = s[j] * inv;
        #pragma unroll
        for (int d = 0; d < 8; d++) {
            float4 vv = vs[j][d];
            acc4[d].x = fmaf(p, vv.x, acc4[d].x);
            acc4[d].y = fmaf(p, vv.y, acc4[d].y);
            acc4[d].z = fmaf(p, vv.z, acc4[d].z);
            acc4[d].w = fmaf(p, vv.w, acc4[d].w);
        }
    }

    float* op = o + (size_t)m * 256 + head * 32;
    #pragma unroll
    for (int d = 0; d < 8; d++) ((float4*)op)[d] = acc4[d];
}

// ---------------------------------------------------------------------------
// Kernel 3: output projection GEMM.
//   proj[m, n] = sum_k o[m,k] * w_out[n,k] + b_out[n]   (A row-major now)
// ---------------------------------------------------------------------------
__global__ __launch_bounds__(256) void out_gemm_kernel(
    const float* __restrict__ A, const float* __restrict__ w,
    const float* __restrict__ bias, float* __restrict__ out)
{
    __shared__ float As[BK][BM];
    __shared__ float Bs[BK][BN];

    const int tid = threadIdx.x;
    const int tx = tid & 15;
    const int ty = tid >> 4;
    const int n0 = blockIdx.x * BN;   // 2 tiles
    const int m0 = blockIdx.y * BM;

    // A loader (row-major, transpose into As[k][m])
    const int aRowM = tid >> 1;        // local m 0..127
    const int aSeg = (tid & 1) * 8;    // k sub-offset
    // B loader identical to kernel 1
    const int bRowN = tid >> 1;
    const int bSeg = (tid & 1) * 8;

    float4 aR0, aR1, bR0, bR1;
    {
        const float* ap = A + (size_t)(m0 + aRowM) * 256 + aSeg;
        aR0 = *(const float4*)(ap);
        aR1 = *(const float4*)(ap + 4);
        const float* wp = w + (size_t)(n0 + bRowN) * 256 + bSeg;
        bR0 = *(const float4*)(wp);
        bR1 = *(const float4*)(wp + 4);
    }
    As[aSeg + 0][aRowM] = aR0.x; As[aSeg + 1][aRowM] = aR0.y;
    As[aSeg + 2][aRowM] = aR0.z; As[aSeg + 3][aRowM] = aR0.w;
    As[aSeg + 4][aRowM] = aR1.x; As[aSeg + 5][aRowM] = aR1.y;
    As[aSeg + 6][aRowM] = aR1.z; As[aSeg + 7][aRowM] = aR1.w;
    Bs[bSeg + 0][bRowN] = bR0.x; Bs[bSeg + 1][bRowN] = bR0.y;
    Bs[bSeg + 2][bRowN] = bR0.z; Bs[bSeg + 3][bRowN] = bR0.w;
    Bs[bSeg + 4][bRowN] = bR1.x; Bs[bSeg + 5][bRowN] = bR1.y;
    Bs[bSeg + 6][bRowN] = bR1.z; Bs[bSeg + 7][bRowN] = bR1.w;
    __syncthreads();

    float acc[8][8];
    #pragma unroll
    for (int i = 0; i < 8; i++)
        #pragma unroll
        for (int j = 0; j < 8; j++) acc[i][j] = 0.f;

    #pragma unroll 1
    for (int kt = 0; kt < 16; kt++) {
        if (kt < 15) {
            const int k0 = (kt + 1) * BK;
            const float* ap = A + (size_t)(m0 + aRowM) * 256 + k0 + aSeg;
            aR0 = *(const float4*)(ap);
            aR1 = *(const float4*)(ap + 4);
            const float* wp = w + (size_t)(n0 + bRowN) * 256 + k0 + bSeg;
            bR0 = *(const float4*)(wp);
            bR1 = *(const float4*)(wp + 4);
        }
        #pragma unroll
        for (int kk = 0; kk < BK; kk++) {
            float a[8], b[8];
            *(float4*)&a[0] = *(float4*)&As[kk][ty * 8];
            *(float4*)&a[4] = *(float4*)&As[kk][ty * 8 + 4];
            *(float4*)&b[0] = *(float4*)&Bs[kk][tx * 8];
            *(float4*)&b[4] = *(float4*)&Bs[kk][tx * 8 + 4];
            #pragma unroll
            for (int i = 0; i < 8; i++)
                #pragma unroll
                for (int j = 0; j < 8; j++)
                    acc[i][j] = fmaf(a[i], b[j], acc[i][j]);
        }
        __syncthreads();
        if (kt < 15) {
            As[aSeg + 0][aRowM] = aR0.x; As[aSeg + 1][aRowM] = aR0.y;
            As[aSeg + 2][aRowM] = aR0.z; As[aSeg + 3][aRowM] = aR0.w;
            As[aSeg + 4][aRowM] = aR1.x; As[aSeg + 5][aRowM] = aR1.y;
            As[aSeg + 6][aRowM] = aR1.z; As[aSeg + 7][aRowM] = aR1.w;
            Bs[bSeg + 0][bRowN] = bR0.x; Bs[bSeg + 1][bRowN] = bR0.y;
            Bs[bSeg + 2][bRowN] = bR0.z; Bs[bSeg + 3][bRowN] = bR0.w;
            Bs[bSeg + 4][bRowN] = bR1.x; Bs[bSeg + 5][bRowN] = bR1.y;
            Bs[bSeg + 6][bRowN] = bR1.z; Bs[bSeg + 7][bRowN] = bR1.w;
            __syncthreads();
        }
    }

    float4 bv0 = *(const float4*)(bias + n0 + tx * 8);
    float4 bv1 = *(const float4*)(bias + n0 + tx * 8 + 4);
    #pragma unroll
    for (int i = 0; i < 8; i++) {
        size_t row = (size_t)(m0 + ty * 8 + i) * 256 + n0 + tx * 8;
        float4 o0 = make_float4(acc[i][0] + bv0.x, acc[i][1] + bv0.y,
                                acc[i][2] + bv0.z, acc[i][3] + bv0.w);
        float4 o1 = make_float4(acc[i][4] + bv1.x, acc[i][5] + bv1.y,
                                acc[i][6] + bv1.z, acc[i][7] + bv1.w);
        *(float4*)(out + row) = o0;
        *(float4*)(out + row + 4) = o1;
    }
}

// ---------------------------------------------------------------------------
// Kernel 4: LayerNorm over channels + NHWC->NCHW transpose.
// One block handles 32 consecutive tokens (same b, same h row, w contiguous).
// ---------------------------------------------------------------------------
__global__ __launch_bounds__(256) void ln_kernel(
    const float* __restrict__ proj, const float* __restrict__ gamma,
    const float* __restrict__ beta, float* __restrict__ out)
{
    __shared__ float sm[32][257];   // odd pad -> conflict-free transposed reads
    __shared__ float smu[32], srs[32];

    const int tid = threadIdx.x;
    const int lane = tid & 31;
    const int wp = tid >> 5;        // warp id 0..7
    const int m0 = blockIdx.x * 32;
    const int b = m0 >> 16;
    const int hw = m0 & 65535;

    // load 32 x 256 tile (coalesced float4 reads)
    #pragma unroll
    for (int i = 0; i < 8; i++) {
        int idx = tid + 256 * i;        // 0..2047 float4 slots
        int r = idx >> 6;               // token 0..31
        int c4 = idx & 63;              // float4 col
        float4 v = *(const float4*)(proj + (size_t)(m0 + r) * 256 + c4 * 4);
        sm[r][c4 * 4 + 0] = v.x;
        sm[r][c4 * 4 + 1] = v.y;
        sm[r][c4 * 4 + 2] = v.z;
        sm[r][c4 * 4 + 3] = v.w;
    }
    __syncthreads();

    // per-token mean/var (warp wp handles rows wp*4 .. wp*4+3)
    #pragma unroll
    for (int rr = 0; rr < 4; rr++) {
        int r = wp * 4 + rr;
        float sum = 0.f, sq = 0.f;
        #pragma unroll
        for (int u = 0; u < 8; u++) {
            float v = sm[r][lane + 32 * u];   // stride-32 -> conflict free
            sum += v;
            sq = fmaf(v, v, sq);
        }
        #pragma unroll
        for (int off = 16; off > 0; off >>= 1) {
            sum += __shfl_xor_sync(0xFFFFFFFFu, sum, off);
            sq  += __shfl_xor_sync(0xFFFFFFFFu, sq, off);
        }
        if (lane == 0) {
            float mu = sum * (1.f / 256.f);
            smu[r] = mu;
            srs[r] = rsqrtf(sq * (1.f / 256.f) - mu * mu + 1e-5f);
        }
    }
    __syncthreads();

    // write NCHW: out[(b*256 + c)*65536 + hw + lane], warp handles c block of 32
    #pragma unroll
    for (int it = 0; it < 32; it++) {
        int c = wp * 32 + it;               // uniform within warp
        float g = gamma[c], be = beta[c];
        float v = (sm[lane][c] - smu[lane]) * srs[lane] * g + be;
        out[(size_t)(b * 256 + c) * 65536 + hw + lane] = v;
    }
}

// ---------------------------------------------------------------------------
// Launch
// ---------------------------------------------------------------------------
extern "C" void kernel_launch(void* const* d_in, const int* in_sizes, int n_in,
                              void* d_out, int out_size)
{
    const float* x     = (const float*)d_in[0];
    const float* w_in  = (const float*)d_in[1];
    const float* b_in  = (const float*)d_in[2];
    const float* w_out = (const float*)d_in[3];
    const float* b_out = (const float*)d_in[4];
    const float* gamma = (const float*)d_in[5];
    const float* beta  = (const float*)d_in[6];
    float* out = (float*)d_out;

    float* qkv;  cudaGetSymbolAddress((void**)&qkv,  g_qkv);
    float* obuf; cudaGetSymbolAddress((void**)&obuf, g_o);
    float* proj; cudaGetSymbolAddress((void**)&proj, g_proj);

    // 1) QKV projection: grid x = n-tiles (fast) so the 6 n-tiles sharing one
    //    A m-tile run concurrently and reuse A through L2.
    qkv_gemm_kernel<<<dim3(6, 2048), 256>>>(x, w_in, b_in, qkv);

    // 2) Windowed attention: one block per (window, head)
    attn_kernel<<<NWIN * HEADS, 64>>>(qkv, obuf);

    // 3) Output projection
    out_gemm_kernel<<<dim3(2, 2048), 256>>>(obuf, w_out, b_out, proj);

    // 4) LayerNorm + transpose to NCHW
    ln_kernel<<<M_TOK / 32, 256>>>(proj, gamma, beta, out);
}

// round 12
// speedup vs baseline: 1.6979x; 1.6979x over previous
#include <cuda_runtime.h>
#include <cuda_bf16.h>
#include <cstdint>
#include <cstddef>

// Problem constants
// x: [B=4, C=256, H=256, W=256], tokens M = B*H*W = 262144
#define M_TOK 262144
#define CDIM 256
#define HEADS 8
#define HD 32
#define WIN 8
#define TWIN 64
#define NWIN 4096

// ---------------------------------------------------------------------------
// Scratch (static __device__ arrays — allocation-free per harness rules)
// ---------------------------------------------------------------------------
__device__ float g_qkv[(size_t)M_TOK * 768];          // 805 MB
__device__ float g_proj[(size_t)M_TOK * CDIM];        // 268 MB
__device__ __nv_bfloat16 g_xh[(size_t)M_TOK * CDIM];  // x transposed, hi
__device__ __nv_bfloat16 g_xl[(size_t)M_TOK * CDIM];  // x transposed, lo
__device__ __nv_bfloat16 g_oh[(size_t)M_TOK * CDIM];  // attn out, hi
__device__ __nv_bfloat16 g_ol[(size_t)M_TOK * CDIM];  // attn out, lo
__device__ __nv_bfloat16 g_wih[768 * 256], g_wil[768 * 256];
__device__ __nv_bfloat16 g_woh[256 * 256], g_wol[256 * 256];

// ---------------------------------------------------------------------------
// PTX helpers (compute_103-safe: cp.async + ldmatrix + mma.sync only)
// ---------------------------------------------------------------------------
__device__ __forceinline__ uint32_t smem_u32(const void* p) {
    uint32_t a;
    asm("{ .reg .u64 t; cvta.to.shared.u64 t, %1; cvt.u32.u64 %0, t; }"
        : "=r"(a) : "l"(p));
    return a;
}

__device__ __forceinline__ void cp16(uint32_t dst, const void* src) {
    asm volatile("cp.async.cg.shared.global [%0], [%1], 16;"
                 :: "r"(dst), "l"(src));
}

#define LDSM4(r, a) \
    asm volatile("ldmatrix.sync.aligned.m8n8.x4.shared.b16 {%0,%1,%2,%3}, [%4];" \
        : "=r"((r)[0]), "=r"((r)[1]), "=r"((r)[2]), "=r"((r)[3]) : "r"(a))

#define MMA16816(c, a, b0, b1) \
    asm volatile("mma.sync.aligned.m16n8k16.row.col.f32.bf16.bf16.f32 " \
        "{%0,%1,%2,%3}, {%4,%5,%6,%7}, {%8,%9}, {%0,%1,%2,%3};" \
        : "+f"((c)[0]), "+f"((c)[1]), "+f"((c)[2]), "+f"((c)[3]) \
        : "r"((a)[0]), "r"((a)[1]), "r"((a)[2]), "r"((a)[3]), "r"(b0), "r"(b1))

// ---------------------------------------------------------------------------
// Split kernels: fp32 -> (bf16 hi, bf16 lo)
// ---------------------------------------------------------------------------
__global__ __launch_bounds__(256) void split_small_kernel(
    const float* __restrict__ in, __nv_bfloat16* __restrict__ hi,
    __nv_bfloat16* __restrict__ lo, int n)
{
    int i = blockIdx.x * 256 + threadIdx.x;
    if (i < n) {
        float v = in[i];
        __nv_bfloat16 h = __float2bfloat16(v);
        hi[i] = h;
        lo[i] = __float2bfloat16(v - __bfloat162float(h));
    }
}

// x [4][256][65536] NCHW -> xT [m][256] bf16 hi/lo (transpose + split)
__global__ __launch_bounds__(256) void split_x_kernel(
    const float* __restrict__ x, __nv_bfloat16* __restrict__ hi,
    __nv_bfloat16* __restrict__ lo)
{
    __shared__ float s[32][132];
    const int tid = threadIdx.x;
    const int m0 = blockIdx.x * 128;
    const int c0 = blockIdx.y * 32;
    const int b = m0 >> 16;
    const int hw0 = m0 & 65535;
    const float* xb = x + ((size_t)b * 256 + c0) * 65536 + hw0;

    #pragma unroll
    for (int i = 0; i < 4; i++) {
        int idx = tid + 256 * i;       // 1024 float4 slots = 32c x 32(m4)
        int c = idx >> 5, m4 = idx & 31;
        float4 v = *(const float4*)(xb + (size_t)c * 65536 + m4 * 4);
        *(float4*)&s[c][m4 * 4] = v;
    }
    __syncthreads();

    const int m = tid >> 1;
    const int half = tid & 1;
    uint32_t hp[8], lp[8];
    #pragma unroll
    for (int p = 0; p < 8; p++) {
        float a = s[half * 16 + 2 * p][m];
        float bb = s[half * 16 + 2 * p + 1][m];
        __nv_bfloat162 hh = __floats2bfloat162_rn(a, bb);
        float ra = a - __bfloat162float(hh.x);
        float rb = bb - __bfloat162float(hh.y);
        __nv_bfloat162 ll = __floats2bfloat162_rn(ra, rb);
        hp[p] = *reinterpret_cast<uint32_t*>(&hh);
        lp[p] = *reinterpret_cast<uint32_t*>(&ll);
    }
    size_t o = (size_t)(m0 + m) * 256 + c0 + half * 16;
    ((uint4*)(hi + o))[0] = make_uint4(hp[0], hp[1], hp[2], hp[3]);
    ((uint4*)(hi + o))[1] = make_uint4(hp[4], hp[5], hp[6], hp[7]);
    ((uint4*)(lo + o))[0] = make_uint4(lp[0], lp[1], lp[2], lp[3]);
    ((uint4*)(lo + o))[1] = make_uint4(lp[4], lp[5], lp[6], lp[7]);
}

// ---------------------------------------------------------------------------
// bf16 mma.sync GEMM: out[m, n] = sum_k A[m,k]*B[n,k] + bias[n]
//  A,B as bf16 hi/lo pairs, K = 256. CTA tile 128x128, BK=32, 2-stage cp.async.
//  3-term compensated product: Ah*Bh + Ah*Bl + Al*Bh (fp32 accum).
//  8 warps (4m x 2n), each 32x64 via m16n8k16.
//  SMEM tiles: 128 rows x 40 bf16 (stride 80B -> conflict-free ldmatrix).
// ---------------------------------------------------------------------------
#define TILE_B 10240           // 128 * 80 bytes
#define STAGE_B (4 * TILE_B)   // Ah, Al, Bh, Bl
#define GEMM_SMEM (2 * STAGE_B)

__device__ __forceinline__ void load_tile32(uint32_t dst, const __nv_bfloat16* src,
                                            int r0, int k0, int tid) {
    #pragma unroll
    for (int i = 0; i < 2; i++) {
        int idx = tid + 256 * i;          // 512 x 16B chunks
        int row = idx >> 2, cc = idx & 3;
        cp16(dst + row * 80 + cc * 16,
             src + (size_t)(r0 + row) * 256 + k0 + cc * 8);
    }
}

__global__ __launch_bounds__(256) void mma_gemm_kernel(
    const __nv_bfloat16* __restrict__ Ah, const __nv_bfloat16* __restrict__ Al,
    const __nv_bfloat16* __restrict__ Bh, const __nv_bfloat16* __restrict__ Bl,
    const float* __restrict__ bias, float* __restrict__ out, int ldout)
{
    extern __shared__ char smem[];
    const int tid = threadIdx.x;
    const int wid = tid >> 5, lane = tid & 31;
    const int wm = wid & 3, wn = wid >> 2;       // 4 x 2 warp grid
    const int n0 = blockIdx.x * 128, m0 = blockIdx.y * 128;
    const uint32_t sb = smem_u32(smem);

    // ldmatrix address components (bytes)
    const uint32_t aRowB = (uint32_t)(wm * 32 + (lane & 15)) * 80 + (lane >> 4) * 16;
    const uint32_t bRowB = (uint32_t)(wn * 64 + (lane >> 4) * 8 + (lane & 7)) * 80
                         + ((lane >> 3) & 1) * 16;

    #define LOAD_STAGE(s) do {                                   \
        int _k = (s) * 32;                                       \
        uint32_t _b = sb + ((s) & 1) * STAGE_B;                  \
        load_tile32(_b,              Ah, m0, _k, tid);           \
        load_tile32(_b + TILE_B,     Al, m0, _k, tid);           \
        load_tile32(_b + 2 * TILE_B, Bh, n0, _k, tid);           \
        load_tile32(_b + 3 * TILE_B, Bl, n0, _k, tid);           \
        asm volatile("cp.async.commit_group;" ::: "memory");     \
    } while (0)

    LOAD_STAGE(0);
    LOAD_STAGE(1);

    float c[2][8][4];
    #pragma unroll
    for (int mi = 0; mi < 2; mi++)
        #pragma unroll
        for (int nj = 0; nj < 8; nj++)
            #pragma unroll
            for (int q = 0; q < 4; q++) c[mi][nj][q] = 0.f;

    #pragma unroll 1
    for (int s = 0; s < 8; s++) {
        if (s < 7) asm volatile("cp.async.wait_group 1;" ::: "memory");
        else       asm volatile("cp.async.wait_group 0;" ::: "memory");
        __syncthreads();

        const uint32_t base = sb + (s & 1) * STAGE_B;
        #pragma unroll
        for (int kk = 0; kk < 2; kk++) {
            const uint32_t ko = kk * 32;   // 16 bf16 = 32 bytes
            uint32_t ah[2][4], al[2][4], bh[4][4], bl[4][4];
            #pragma unroll
            for (int mi = 0; mi < 2; mi++) {
                uint32_t ra = base + aRowB + mi * 16 * 80 + ko;
                LDSM4(ah[mi], ra);
                LDSM4(al[mi], ra + TILE_B);
            }
            #pragma unroll
            for (int g = 0; g < 4; g++) {
                uint32_t rb = base + 2 * TILE_B + bRowB + g * 16 * 80 + ko;
                LDSM4(bh[g], rb);
                LDSM4(bl[g], rb + TILE_B);
            }
            #pragma unroll
            for (int mi = 0; mi < 2; mi++)
                #pragma unroll
                for (int g = 0; g < 4; g++)
                    #pragma unroll
                    for (int h = 0; h < 2; h++) {
                        float* cc = c[mi][2 * g + h];
                        MMA16816(cc, ah[mi], bh[g][2 * h], bh[g][2 * h + 1]);
                        MMA16816(cc, ah[mi], bl[g][2 * h], bl[g][2 * h + 1]);
                        MMA16816(cc, al[mi], bh[g][2 * h], bh[g][2 * h + 1]);
                    }
        }
        __syncthreads();
        if (s + 2 < 8) LOAD_STAGE(s + 2);
    }
    #undef LOAD_STAGE

    // Epilogue: bias + float2 fragment stores
    #pragma unroll
    for (int mi = 0; mi < 2; mi++) {
        const int row = m0 + wm * 32 + mi * 16 + (lane >> 2);
        #pragma unroll
        for (int nj = 0; nj < 8; nj++) {
            const int col = n0 + wn * 64 + nj * 8 + (lane & 3) * 2;
            const float2 bv = *(const float2*)(bias + col);
            float2 v0 = make_float2(c[mi][nj][0] + bv.x, c[mi][nj][1] + bv.y);
            float2 v1 = make_float2(c[mi][nj][2] + bv.x, c[mi][nj][3] + bv.y);
            *(float2*)(out + (size_t)row * ldout + col) = v0;
            *(float2*)(out + (size_t)(row + 8) * ldout + col) = v1;
        }
    }
}

// ---------------------------------------------------------------------------
// Windowed attention (fp32). One 64-thread block per (window, head).
// Outputs bf16 hi/lo directly for the out-proj GEMM.
// ---------------------------------------------------------------------------
__global__ __launch_bounds__(64) void attn_kernel(
    const float* __restrict__ qkv,
    __nv_bfloat16* __restrict__ o_hi, __nv_bfloat16* __restrict__ o_lo)
{
    const int bid = blockIdx.x;
    const int head = bid & 7;
    const int win = bid >> 3;
    const int b = win >> 10;
    const int rem = win & 1023;
    const int hn = rem >> 5, wn = rem & 31;

    const int t = threadIdx.x;
    const int s1 = t >> 3, s2 = t & 7;
    const int m = (b << 16) + ((hn * 8 + s1) << 8) + (wn * 8 + s2);

    __shared__ float4 ks[TWIN][8];
    __shared__ float4 vs[TWIN][8];

    const float* qp = qkv + (size_t)m * 768 + head * 32;
    float4 q[8];
    #pragma unroll
    for (int d = 0; d < 8; d++) {
        q[d]     = ((const float4*)(qp))[d];
        ks[t][d] = ((const float4*)(qp + 256))[d];
        vs[t][d] = ((const float4*)(qp + 512))[d];
    }
    __syncthreads();

    float s[TWIN];
    #pragma unroll
    for (int j = 0; j < TWIN; j++) {
        float acc = 0.f;
        #pragma unroll
        for (int d = 0; d < 8; d++) {
            float4 kv = ks[j][d];
            acc = fmaf(q[d].x, kv.x, acc);
            acc = fmaf(q[d].y, kv.y, acc);
            acc = fmaf(q[d].z, kv.z, acc);
            acc = fmaf(q[d].w, kv.w, acc);
        }
        s[j] = acc * 0.17677669529663687f;
    }

    float mx = s[0];
    #pragma unroll
    for (int j = 1; j < TWIN; j++) mx = fmaxf(mx, s[j]);
    float sum = 0.f;
    #pragma unroll
    for (int j = 0; j < TWIN; j++) { s[j] = __expf(s[j] - mx); sum += s[j]; }
    const float inv = 1.f / sum;

    float4 acc4[8];
    #pragma unroll
    for (int d = 0; d < 8; d++) acc4[d] = make_float4(0.f, 0.f, 0.f, 0.f);
    #pragma unroll
    for (int j = 0; j < TWIN; j++) {
        const float p = s[j] * inv;
        #pragma unroll
        for (int d = 0; d < 8; d++) {
            float4 vv = vs[j][d];
            acc4[d].x = fmaf(p, vv.x, acc4[d].x);
            acc4[d].y = fmaf(p, vv.y, acc4[d].y);
            acc4[d].z = fmaf(p, vv.z, acc4[d].z);
            acc4[d].w = fmaf(p, vv.w, acc4[d].w);
        }
    }

    float va[32];
    #pragma unroll
    for (int d = 0; d < 8; d++) {
        va[d * 4 + 0] = acc4[d].x; va[d * 4 + 1] = acc4[d].y;
        va[d * 4 + 2] = acc4[d].z; va[d * 4 + 3] = acc4[d].w;
    }
    uint32_t hp[16], lp[16];
    #pragma unroll
    for (int p = 0; p < 16; p++) {
        float a = va[2 * p], bb = va[2 * p + 1];
        __nv_bfloat162 hh = __floats2bfloat162_rn(a, bb);
        float ra = a - __bfloat162float(hh.x);
        float rb = bb - __bfloat162float(hh.y);
        __nv_bfloat162 ll = __floats2bfloat162_rn(ra, rb);
        hp[p] = *reinterpret_cast<uint32_t*>(&hh);
        lp[p] = *reinterpret_cast<uint32_t*>(&ll);
    }
    uint4* oh = (uint4*)(o_hi + (size_t)m * 256 + head * 32);
    uint4* ol = (uint4*)(o_lo + (size_t)m * 256 + head * 32);
    oh[0] = make_uint4(hp[0], hp[1], hp[2], hp[3]);
    oh[1] = make_uint4(hp[4], hp[5], hp[6], hp[7]);
    oh[2] = make_uint4(hp[8], hp[9], hp[10], hp[11]);
    oh[3] = make_uint4(hp[12], hp[13], hp[14], hp[15]);
    ol[0] = make_uint4(lp[0], lp[1], lp[2], lp[3]);
    ol[1] = make_uint4(lp[4], lp[5], lp[6], lp[7]);
    ol[2] = make_uint4(lp[8], lp[9], lp[10], lp[11]);
    ol[3] = make_uint4(lp[12], lp[13], lp[14], lp[15]);
}

// ---------------------------------------------------------------------------
// LayerNorm over channels + NHWC->NCHW transpose
// ---------------------------------------------------------------------------
__global__ __launch_bounds__(256) void ln_kernel(
    const float* __restrict__ proj, const float* __restrict__ gamma,
    const float* __restrict__ beta, float* __restrict__ out)
{
    __shared__ float sm[32][257];
    __shared__ float smu[32], srs[32];

    const int tid = threadIdx.x;
    const int lane = tid & 31;
    const int wp = tid >> 5;
    const int m0 = blockIdx.x * 32;
    const int b = m0 >> 16;
    const int hw = m0 & 65535;

    #pragma unroll
    for (int i = 0; i < 8; i++) {
        int idx = tid + 256 * i;
        int r = idx >> 6;
        int c4 = idx & 63;
        float4 v = *(const float4*)(proj + (size_t)(m0 + r) * 256 + c4 * 4);
        sm[r][c4 * 4 + 0] = v.x; sm[r][c4 * 4 + 1] = v.y;
        sm[r][c4 * 4 + 2] = v.z; sm[r][c4 * 4 + 3] = v.w;
    }
    __syncthreads();

    #pragma unroll
    for (int rr = 0; rr < 4; rr++) {
        int r = wp * 4 + rr;
        float sum = 0.f, sq = 0.f;
        #pragma unroll
        for (int u = 0; u < 8; u++) {
            float v = sm[r][lane + 32 * u];
            sum += v;
            sq = fmaf(v, v, sq);
        }
        #pragma unroll
        for (int off = 16; off > 0; off >>= 1) {
            sum += __shfl_xor_sync(0xFFFFFFFFu, sum, off);
            sq  += __shfl_xor_sync(0xFFFFFFFFu, sq, off);
        }
        if (lane == 0) {
            float mu = sum * (1.f / 256.f);
            smu[r] = mu;
            srs[r] = rsqrtf(sq * (1.f / 256.f) - mu * mu + 1e-5f);
        }
    }
    __syncthreads();

    #pragma unroll
    for (int it = 0; it < 32; it++) {
        int c = wp * 32 + it;
        float g = gamma[c], be = beta[c];
        float v = (sm[lane][c] - smu[lane]) * srs[lane] * g + be;
        out[(size_t)(b * 256 + c) * 65536 + hw + lane] = v;
    }
}

// ---------------------------------------------------------------------------
// Launch
// ---------------------------------------------------------------------------
extern "C" void kernel_launch(void* const* d_in, const int* in_sizes, int n_in,
                              void* d_out, int out_size)
{
    const float* x     = (const float*)d_in[0];
    const float* w_in  = (const float*)d_in[1];
    const float* b_in  = (const float*)d_in[2];
    const float* w_out = (const float*)d_in[3];
    const float* b_out = (const float*)d_in[4];
    const float* gamma = (const float*)d_in[5];
    const float* beta  = (const float*)d_in[6];
    float* out = (float*)d_out;

    float *qkv, *proj;
    __nv_bfloat16 *xh, *xl, *oh, *ol, *wih, *wil, *woh, *wol;
    cudaGetSymbolAddress((void**)&qkv, g_qkv);
    cudaGetSymbolAddress((void**)&proj, g_proj);
    cudaGetSymbolAddress((void**)&xh, g_xh);
    cudaGetSymbolAddress((void**)&xl, g_xl);
    cudaGetSymbolAddress((void**)&oh, g_oh);
    cudaGetSymbolAddress((void**)&ol, g_ol);
    cudaGetSymbolAddress((void**)&wih, g_wih);
    cudaGetSymbolAddress((void**)&wil, g_wil);
    cudaGetSymbolAddress((void**)&woh, g_woh);
    cudaGetSymbolAddress((void**)&wol, g_wol);

    cudaFuncSetAttribute(mma_gemm_kernel,
                         cudaFuncAttributeMaxDynamicSharedMemorySize, GEMM_SMEM);

    // 0) hi/lo splits (weights + transposed x)
    split_small_kernel<<<(768 * 256 + 255) / 256, 256>>>(w_in, wih, wil, 768 * 256);
    split_small_kernel<<<(256 * 256 + 255) / 256, 256>>>(w_out, woh, wol, 256 * 256);
    split_x_kernel<<<dim3(M_TOK / 128, 8), 256>>>(x, xh, xl);

    // 1) QKV projection on tensor cores (n-tiles fast for L2 A-reuse)
    mma_gemm_kernel<<<dim3(6, M_TOK / 128), 256, GEMM_SMEM>>>(
        xh, xl, wih, wil, b_in, qkv, 768);

    // 2) Windowed attention (fp32), emits bf16 hi/lo
    attn_kernel<<<NWIN * HEADS, 64>>>(qkv, oh, ol);

    // 3) Output projection on tensor cores
    mma_gemm_kernel<<<dim3(2, M_TOK / 128), 256, GEMM_SMEM>>>(
        oh, ol, woh, wol, b_out, proj, 256);

    // 4) LayerNorm + transpose to NCHW
    ln_kernel<<<M_TOK / 32, 256>>>(proj, gamma, beta, out);
}

// round 13
// speedup vs baseline: 1.6999x; 1.0012x over previous
#include <cuda_runtime.h>
#include <cuda_bf16.h>
#include <cstdint>
#include <cstddef>

// Problem constants
// x: [B=4, C=256, H=256, W=256], tokens M = B*H*W = 262144
#define M_TOK 262144
#define CDIM 256
#define HEADS 8
#define HD 32
#define WIN 8
#define TWIN 64
#define NWIN 4096

// ---------------------------------------------------------------------------
// Scratch (static __device__ arrays — allocation-free per harness rules)
// ---------------------------------------------------------------------------
__device__ float g_qkv[(size_t)M_TOK * 768];          // 805 MB
__device__ float g_proj[(size_t)M_TOK * CDIM];        // 268 MB
__device__ __nv_bfloat16 g_xh[(size_t)M_TOK * CDIM];  // x transposed, hi
__device__ __nv_bfloat16 g_xl[(size_t)M_TOK * CDIM];  // x transposed, lo
__device__ __nv_bfloat16 g_oh[(size_t)M_TOK * CDIM];  // attn out, hi
__device__ __nv_bfloat16 g_ol[(size_t)M_TOK * CDIM];  // attn out, lo
__device__ __nv_bfloat16 g_wih[768 * 256], g_wil[768 * 256];
__device__ __nv_bfloat16 g_woh[256 * 256], g_wol[256 * 256];

// ---------------------------------------------------------------------------
// PTX helpers (compute_103-safe: cp.async + ldmatrix + mma.sync only)
// ---------------------------------------------------------------------------
__device__ __forceinline__ uint32_t smem_u32(const void* p) {
    uint32_t a;
    asm("{ .reg .u64 t; cvta.to.shared.u64 t, %1; cvt.u32.u64 %0, t; }"
        : "=r"(a) : "l"(p));
    return a;
}

__device__ __forceinline__ void cp16(uint32_t dst, const void* src) {
    asm volatile("cp.async.cg.shared.global [%0], [%1], 16;"
                 :: "r"(dst), "l"(src));
}

#define LDSM4(r, a) \
    asm volatile("ldmatrix.sync.aligned.m8n8.x4.shared.b16 {%0,%1,%2,%3}, [%4];" \
        : "=r"((r)[0]), "=r"((r)[1]), "=r"((r)[2]), "=r"((r)[3]) : "r"(a))

#define MMA16816(c, a, b0, b1) \
    asm volatile("mma.sync.aligned.m16n8k16.row.col.f32.bf16.bf16.f32 " \
        "{%0,%1,%2,%3}, {%4,%5,%6,%7}, {%8,%9}, {%0,%1,%2,%3};" \
        : "+f"((c)[0]), "+f"((c)[1]), "+f"((c)[2]), "+f"((c)[3]) \
        : "r"((a)[0]), "r"((a)[1]), "r"((a)[2]), "r"((a)[3]), "r"(b0), "r"(b1))

// ---------------------------------------------------------------------------
// Split kernels: fp32 -> (bf16 hi, bf16 lo)
// ---------------------------------------------------------------------------
__global__ __launch_bounds__(256) void split_small_kernel(
    const float* __restrict__ in, __nv_bfloat16* __restrict__ hi,
    __nv_bfloat16* __restrict__ lo, int n)
{
    int i = blockIdx.x * 256 + threadIdx.x;
    if (i < n) {
        float v = in[i];
        __nv_bfloat16 h = __float2bfloat16(v);
        hi[i] = h;
        lo[i] = __float2bfloat16(v - __bfloat162float(h));
    }
}

// x [4][256][65536] NCHW -> xT [m][256] bf16 hi/lo (transpose + split)
__global__ __launch_bounds__(256) void split_x_kernel(
    const float* __restrict__ x, __nv_bfloat16* __restrict__ hi,
    __nv_bfloat16* __restrict__ lo)
{
    __shared__ float s[32][132];
    const int tid = threadIdx.x;
    const int m0 = blockIdx.x * 128;
    const int c0 = blockIdx.y * 32;
    const int b = m0 >> 16;
    const int hw0 = m0 & 65535;
    const float* xb = x + ((size_t)b * 256 + c0) * 65536 + hw0;

    #pragma unroll
    for (int i = 0; i < 4; i++) {
        int idx = tid + 256 * i;       // 1024 float4 slots = 32c x 32(m4)
        int c = idx >> 5, m4 = idx & 31;
        float4 v = *(const float4*)(xb + (size_t)c * 65536 + m4 * 4);
        *(float4*)&s[c][m4 * 4] = v;
    }
    __syncthreads();

    const int m = tid >> 1;
    const int half = tid & 1;
    uint32_t hp[8], lp[8];
    #pragma unroll
    for (int p = 0; p < 8; p++) {
        float a = s[half * 16 + 2 * p][m];
        float bb = s[half * 16 + 2 * p + 1][m];
        __nv_bfloat162 hh = __floats2bfloat162_rn(a, bb);
        float ra = a - __bfloat162float(hh.x);
        float rb = bb - __bfloat162float(hh.y);
        __nv_bfloat162 ll = __floats2bfloat162_rn(ra, rb);
        hp[p] = *reinterpret_cast<uint32_t*>(&hh);
        lp[p] = *reinterpret_cast<uint32_t*>(&ll);
    }
    size_t o = (size_t)(m0 + m) * 256 + c0 + half * 16;
    ((uint4*)(hi + o))[0] = make_uint4(hp[0], hp[1], hp[2], hp[3]);
    ((uint4*)(hi + o))[1] = make_uint4(hp[4], hp[5], hp[6], hp[7]);
    ((uint4*)(lo + o))[0] = make_uint4(lp[0], lp[1], lp[2], lp[3]);
    ((uint4*)(lo + o))[1] = make_uint4(lp[4], lp[5], lp[6], lp[7]);
}

// ---------------------------------------------------------------------------
// bf16 mma.sync GEMM: out[m, n] = sum_k A[m,k]*B[n,k] + bias[n]
//  A,B as bf16 hi/lo pairs, K = 256. CTA tile 128x128, BK=32, 2-stage cp.async.
//  3-term compensated product: Ah*Bh + Ah*Bl + Al*Bh (fp32 accum).
//  8 warps (4m x 2n), each 32x64 via m16n8k16.
//  SMEM tiles: 128 rows x 40 bf16 (stride 80B -> conflict-free ldmatrix).
// ---------------------------------------------------------------------------
#define TILE_B 10240           // 128 * 80 bytes
#define STAGE_B (4 * TILE_B)   // Ah, Al, Bh, Bl
#define GEMM_SMEM (2 * STAGE_B)

__device__ __forceinline__ void load_tile32(uint32_t dst, const __nv_bfloat16* src,
                                            int r0, int k0, int tid) {
    #pragma unroll
    for (int i = 0; i < 2; i++) {
        int idx = tid + 256 * i;          // 512 x 16B chunks
        int row = idx >> 2, cc = idx & 3;
        cp16(dst + row * 80 + cc * 16,
             src + (size_t)(r0 + row) * 256 + k0 + cc * 8);
    }
}

__global__ __launch_bounds__(256) void mma_gemm_kernel(
    const __nv_bfloat16* __restrict__ Ah, const __nv_bfloat16* __restrict__ Al,
    const __nv_bfloat16* __restrict__ Bh, const __nv_bfloat16* __restrict__ Bl,
    const float* __restrict__ bias, float* __restrict__ out, int ldout)
{
    extern __shared__ char smem[];
    const int tid = threadIdx.x;
    const int wid = tid >> 5, lane = tid & 31;
    const int wm = wid & 3, wn = wid >> 2;       // 4 x 2 warp grid
    const int n0 = blockIdx.x * 128, m0 = blockIdx.y * 128;
    const uint32_t sb = smem_u32(smem);

    // ldmatrix address components (bytes)
    const uint32_t aRowB = (uint32_t)(wm * 32 + (lane & 15)) * 80 + (lane >> 4) * 16;
    const uint32_t bRowB = (uint32_t)(wn * 64 + (lane >> 4) * 8 + (lane & 7)) * 80
                         + ((lane >> 3) & 1) * 16;

    #define LOAD_STAGE(s) do {                                   \
        int _k = (s) * 32;                                       \
        uint32_t _b = sb + ((s) & 1) * STAGE_B;                  \
        load_tile32(_b,              Ah, m0, _k, tid);           \
        load_tile32(_b + TILE_B,     Al, m0, _k, tid);           \
        load_tile32(_b + 2 * TILE_B, Bh, n0, _k, tid);           \
        load_tile32(_b + 3 * TILE_B, Bl, n0, _k, tid);           \
        asm volatile("cp.async.commit_group;" ::: "memory");     \
    } while (0)

    LOAD_STAGE(0);
    LOAD_STAGE(1);

    float c[2][8][4];
    #pragma unroll
    for (int mi = 0; mi < 2; mi++)
        #pragma unroll
        for (int nj = 0; nj < 8; nj++)
            #pragma unroll
            for (int q = 0; q < 4; q++) c[mi][nj][q] = 0.f;

    #pragma unroll 1
    for (int s = 0; s < 8; s++) {
        if (s < 7) asm volatile("cp.async.wait_group 1;" ::: "memory");
        else       asm volatile("cp.async.wait_group 0;" ::: "memory");
        __syncthreads();

        const uint32_t base = sb + (s & 1) * STAGE_B;
        #pragma unroll
        for (int kk = 0; kk < 2; kk++) {
            const uint32_t ko = kk * 32;   // 16 bf16 = 32 bytes
            uint32_t ah[2][4], al[2][4], bh[4][4], bl[4][4];
            #pragma unroll
            for (int mi = 0; mi < 2; mi++) {
                uint32_t ra = base + aRowB + mi * 16 * 80 + ko;
                LDSM4(ah[mi], ra);
                LDSM4(al[mi], ra + TILE_B);
            }
            #pragma unroll
            for (int g = 0; g < 4; g++) {
                uint32_t rb = base + 2 * TILE_B + bRowB + g * 16 * 80 + ko;
                LDSM4(bh[g], rb);
                LDSM4(bl[g], rb + TILE_B);
            }
            #pragma unroll
            for (int mi = 0; mi < 2; mi++)
                #pragma unroll
                for (int g = 0; g < 4; g++)
                    #pragma unroll
                    for (int h = 0; h < 2; h++) {
                        float* cc = c[mi][2 * g + h];
                        MMA16816(cc, ah[mi], bh[g][2 * h], bh[g][2 * h + 1]);
                        MMA16816(cc, ah[mi], bl[g][2 * h], bl[g][2 * h + 1]);
                        MMA16816(cc, al[mi], bh[g][2 * h], bh[g][2 * h + 1]);
                    }
        }
        __syncthreads();
        if (s + 2 < 8) LOAD_STAGE(s + 2);
    }
    #undef LOAD_STAGE

    // Epilogue: bias + float2 fragment stores
    #pragma unroll
    for (int mi = 0; mi < 2; mi++) {
        const int row = m0 + wm * 32 + mi * 16 + (lane >> 2);
        #pragma unroll
        for (int nj = 0; nj < 8; nj++) {
            const int col = n0 + wn * 64 + nj * 8 + (lane & 3) * 2;
            const float2 bv = *(const float2*)(bias + col);
            float2 v0 = make_float2(c[mi][nj][0] + bv.x, c[mi][nj][1] + bv.y);
            float2 v1 = make_float2(c[mi][nj][2] + bv.x, c[mi][nj][3] + bv.y);
            *(float2*)(out + (size_t)row * ldout + col) = v0;
            *(float2*)(out + (size_t)(row + 8) * ldout + col) = v1;
        }
    }
}

// ---------------------------------------------------------------------------
// Windowed attention (fp32). One 64-thread block per (window, head).
// Outputs bf16 hi/lo directly for the out-proj GEMM.
// ---------------------------------------------------------------------------
__global__ __launch_bounds__(64) void attn_kernel(
    const float* __restrict__ qkv,
    __nv_bfloat16* __restrict__ o_hi, __nv_bfloat16* __restrict__ o_lo)
{
    const int bid = blockIdx.x;
    const int head = bid & 7;
    const int win = bid >> 3;
    const int b = win >> 10;
    const int rem = win & 1023;
    const int hn = rem >> 5, wn = rem & 31;

    const int t = threadIdx.x;
    const int s1 = t >> 3, s2 = t & 7;
    const int m = (b << 16) + ((hn * 8 + s1) << 8) + (wn * 8 + s2);

    __shared__ float4 ks[TWIN][8];
    __shared__ float4 vs[TWIN][8];

    const float* qp = qkv + (size_t)m * 768 + head * 32;
    float4 q[8];
    #pragma unroll
    for (int d = 0; d < 8; d++) {
        q[d]     = ((const float4*)(qp))[d];
        ks[t][d] = ((const float4*)(qp + 256))[d];
        vs[t][d] = ((const float4*)(qp + 512))[d];
    }
    __syncthreads();

    float s[TWIN];
    #pragma unroll
    for (int j = 0; j < TWIN; j++) {
        float acc = 0.f;
        #pragma unroll
        for (int d = 0; d < 8; d++) {
            float4 kv = ks[j][d];
            acc = fmaf(q[d].x, kv.x, acc);
            acc = fmaf(q[d].y, kv.y, acc);
            acc = fmaf(q[d].z, kv.z, acc);
            acc = fmaf(q[d].w, kv.w, acc);
        }
        s[j] = acc * 0.17677669529663687f;
    }

    float mx = s[0];
    #pragma unroll
    for (int j = 1; j < TWIN; j++) mx = fmaxf(mx, s[j]);
    float sum = 0.f;
    #pragma unroll
    for (int j = 0; j < TWIN; j++) { s[j] = __expf(s[j] - mx); sum += s[j]; }
    const float inv = 1.f / sum;

    float4 acc4[8];
    #pragma unroll
    for (int d = 0; d < 8; d++) acc4[d] = make_float4(0.f, 0.f, 0.f, 0.f);
    #pragma unroll
    for (int j = 0; j < TWIN; j++) {
        const float p = s[j] * inv;
        #pragma unroll
        for (int d = 0; d < 8; d++) {
            float4 vv = vs[j][d];
            acc4[d].x = fmaf(p, vv.x, acc4[d].x);
            acc4[d].y = fmaf(p, vv.y, acc4[d].y);
            acc4[d].z = fmaf(p, vv.z, acc4[d].z);
            acc4[d].w = fmaf(p, vv.w, acc4[d].w);
        }
    }

    float va[32];
    #pragma unroll
    for (int d = 0; d < 8; d++) {
        va[d * 4 + 0] = acc4[d].x; va[d * 4 + 1] = acc4[d].y;
        va[d * 4 + 2] = acc4[d].z; va[d * 4 + 3] = acc4[d].w;
    }
    uint32_t hp[16], lp[16];
    #pragma unroll
    for (int p = 0; p < 16; p++) {
        float a = va[2 * p], bb = va[2 * p + 1];
        __nv_bfloat162 hh = __floats2bfloat162_rn(a, bb);
        float ra = a - __bfloat162float(hh.x);
        float rb = bb - __bfloat162float(hh.y);
        __nv_bfloat162 ll = __floats2bfloat162_rn(ra, rb);
        hp[p] = *reinterpret_cast<uint32_t*>(&hh);
        lp[p] = *reinterpret_cast<uint32_t*>(&ll);
    }
    uint4* oh = (uint4*)(o_hi + (size_t)m * 256 + head * 32);
    uint4* ol = (uint4*)(o_lo + (size_t)m * 256 + head * 32);
    oh[0] = make_uint4(hp[0], hp[1], hp[2], hp[3]);
    oh[1] = make_uint4(hp[4], hp[5], hp[6], hp[7]);
    oh[2] = make_uint4(hp[8], hp[9], hp[10], hp[11]);
    oh[3] = make_uint4(hp[12], hp[13], hp[14], hp[15]);
    ol[0] = make_uint4(lp[0], lp[1], lp[2], lp[3]);
    ol[1] = make_uint4(lp[4], lp[5], lp[6], lp[7]);
    ol[2] = make_uint4(lp[8], lp[9], lp[10], lp[11]);
    ol[3] = make_uint4(lp[12], lp[13], lp[14], lp[15]);
}

// ---------------------------------------------------------------------------
// LayerNorm over channels + NHWC->NCHW transpose
// ---------------------------------------------------------------------------
__global__ __launch_bounds__(256) void ln_kernel(
    const float* __restrict__ proj, const float* __restrict__ gamma,
    const float* __restrict__ beta, float* __restrict__ out)
{
    __shared__ float sm[32][257];
    __shared__ float smu[32], srs[32];

    const int tid = threadIdx.x;
    const int lane = tid & 31;
    const int wp = tid >> 5;
    const int m0 = blockIdx.x * 32;
    const int b = m0 >> 16;
    const int hw = m0 & 65535;

    #pragma unroll
    for (int i = 0; i < 8; i++) {
        int idx = tid + 256 * i;
        int r = idx >> 6;
        int c4 = idx & 63;
        float4 v = *(const float4*)(proj + (size_t)(m0 + r) * 256 + c4 * 4);
        sm[r][c4 * 4 + 0] = v.x; sm[r][c4 * 4 + 1] = v.y;
        sm[r][c4 * 4 + 2] = v.z; sm[r][c4 * 4 + 3] = v.w;
    }
    __syncthreads();

    #pragma unroll
    for (int rr = 0; rr < 4; rr++) {
        int r = wp * 4 + rr;
        float sum = 0.f, sq = 0.f;
        #pragma unroll
        for (int u = 0; u < 8; u++) {
            float v = sm[r][lane + 32 * u];
            sum += v;
            sq = fmaf(v, v, sq);
        }
        #pragma unroll
        for (int off = 16; off > 0; off >>= 1) {
            sum += __shfl_xor_sync(0xFFFFFFFFu, sum, off);
            sq  += __shfl_xor_sync(0xFFFFFFFFu, sq, off);
        }
        if (lane == 0) {
            float mu = sum * (1.f / 256.f);
            smu[r] = mu;
            srs[r] = rsqrtf(sq * (1.f / 256.f) - mu * mu + 1e-5f);
        }
    }
    __syncthreads();

    #pragma unroll
    for (int it = 0; it < 32; it++) {
        int c = wp * 32 + it;
        float g = gamma[c], be = beta[c];
        float v = (sm[lane][c] - smu[lane]) * srs[lane] * g + be;
        out[(size_t)(b * 256 + c) * 65536 + hw + lane] = v;
    }
}

// ---------------------------------------------------------------------------
// Launch
// ---------------------------------------------------------------------------
extern "C" void kernel_launch(void* const* d_in, const int* in_sizes, int n_in,
                              void* d_out, int out_size)
{
    const float* x     = (const float*)d_in[0];
    const float* w_in  = (const float*)d_in[1];
    const float* b_in  = (const float*)d_in[2];
    const float* w_out = (const float*)d_in[3];
    const float* b_out = (const float*)d_in[4];
    const float* gamma = (const float*)d_in[5];
    const float* beta  = (const float*)d_in[6];
    float* out = (float*)d_out;

    float *qkv, *proj;
    __nv_bfloat16 *xh, *xl, *oh, *ol, *wih, *wil, *woh, *wol;
    cudaGetSymbolAddress((void**)&qkv, g_qkv);
    cudaGetSymbolAddress((void**)&proj, g_proj);
    cudaGetSymbolAddress((void**)&xh, g_xh);
    cudaGetSymbolAddress((void**)&xl, g_xl);
    cudaGetSymbolAddress((void**)&oh, g_oh);
    cudaGetSymbolAddress((void**)&ol, g_ol);
    cudaGetSymbolAddress((void**)&wih, g_wih);
    cudaGetSymbolAddress((void**)&wil, g_wil);
    cudaGetSymbolAddress((void**)&woh, g_woh);
    cudaGetSymbolAddress((void**)&wol, g_wol);

    cudaFuncSetAttribute(mma_gemm_kernel,
                         cudaFuncAttributeMaxDynamicSharedMemorySize, GEMM_SMEM);

    // 0) hi/lo splits (weights + transposed x)
    split_small_kernel<<<(768 * 256 + 255) / 256, 256>>>(w_in, wih, wil, 768 * 256);
    split_small_kernel<<<(256 * 256 + 255) / 256, 256>>>(w_out, woh, wol, 256 * 256);
    split_x_kernel<<<dim3(M_TOK / 128, 8), 256>>>(x, xh, xl);

    // 1) QKV projection on tensor cores (n-tiles fast for L2 A-reuse)
    mma_gemm_kernel<<<dim3(6, M_TOK / 128), 256, GEMM_SMEM>>>(
        xh, xl, wih, wil, b_in, qkv, 768);

    // 2) Windowed attention (fp32), emits bf16 hi/lo
    attn_kernel<<<NWIN * HEADS, 64>>>(qkv, oh, ol);

    // 3) Output projection on tensor cores
    mma_gemm_kernel<<<dim3(2, M_TOK / 128), 256, GEMM_SMEM>>>(
        oh, ol, woh, wol, b_out, proj, 256);

    // 4) LayerNorm + transpose to NCHW
    ln_kernel<<<M_TOK / 32, 256>>>(proj, gamma, beta, out);
}